// round 4
// baseline (speedup 1.0000x reference)
#include <cuda_runtime.h>
#include <cstdint>

#define NROWS 8192
#define MCOLS 8192
#define D_DIM 256
#define GAMMA_F (1.0f/256.0f)

// ---- cg2 tensor-core path tiling: effective tile 256(M) x 256(N) per cluster ----
#define BMH 128            // per-CTA M rows
#define BN  256            // full N per tile
#define BK  32             // k-block floats = 128B per row
#define NBLK (D_DIM/BK)    // 8
#define BUFS 3

// smem byte offsets (dynamic smem)
#define SM_TMEMP 0
#define SM_FULL  16        // 3 mbars x 8B (used on leader)
#define SM_DONE  48        // 3 mbars x 8B (per CTA)
#define SM_FIN   80        // 1 mbar
#define SM_SSQ   128       // 256 floats
#define SM_TILE0 2048      // per buf: A 16KB then B 16KB
#define BUF_SZ   32768
#define SM_TOTAL (SM_TILE0 + BUFS*BUF_SZ)   // 100352 B -> occ 2

// tf32 cg2 idesc: c=F32(1@4), a=TF32(2@7), b=TF32(2@10), N/8@17, M/16@24 (M=256)
#define IDESC ((1u<<4) | (2u<<7) | (2u<<10) | ((BN/8u)<<17) | (16u<<24))

// SW128 K-major smem descriptor: layout=2, version=1, SBO=64, LBO=1
#define DESC_BASE ((2ull<<61) | (1ull<<46) | (64ull<<32) | (1ull<<16))
#define MAKE_DESC(a) (DESC_BASE | ((uint64_t)((a) >> 4) & 0x3FFF))

#if defined(__CUDA_ARCH__) && (defined(__CUDA_ARCH_FEAT_SM103_ALL) || defined(__CUDA_ARCH_FEAT_SM100_ALL) || (defined(__CUDA_ARCH_SPECIFIC__) && (__CUDA_ARCH_SPECIFIC__ >= 1000)))
#define TC_OK 1
#else
#define TC_OK 0
#endif

__device__ float g_xsq[NROWS];
__device__ float g_ssq[MCOLS];

// ---------------- PTX helpers ----------------
__device__ __forceinline__ uint32_t smem_u32(const void* p) {
    uint32_t a;
    asm("{ .reg .u64 t; cvta.to.shared.u64 t, %1; cvt.u32.u64 %0, t; }" : "=r"(a) : "l"(p));
    return a;
}
__device__ __forceinline__ bool elect_one() {
    uint32_t pred;
    asm volatile("{ .reg .pred p; elect.sync _|p, 0xFFFFFFFF; selp.b32 %0, 1, 0, p; }" : "=r"(pred));
    return pred != 0;
}
__device__ __forceinline__ uint32_t ctarank() {
    uint32_t r;
    asm("mov.u32 %0, %%cluster_ctarank;" : "=r"(r));
    return r;
}
__device__ __forceinline__ void cp16(uint32_t dst, const void* src) {
    asm volatile("cp.async.cg.shared.global [%0], [%1], 16;" :: "r"(dst), "l"(src));
}
__device__ __forceinline__ void cp_commit() { asm volatile("cp.async.commit_group;" ::: "memory"); }
template<int N> __device__ __forceinline__ void cp_wait() {
    asm volatile("cp.async.wait_group %0;" :: "n"(N) : "memory");
}
__device__ __forceinline__ void mbar_init(uint32_t a, uint32_t cnt) {
    asm volatile("mbarrier.init.shared.b64 [%0], %1;" :: "r"(a), "r"(cnt) : "memory");
}
__device__ __forceinline__ void mbar_wait(uint32_t a, uint32_t parity) {
    asm volatile(
        "{\n\t.reg .pred P1;\n\t"
        "WL_%=:\n\t"
        "mbarrier.try_wait.parity.acquire.cta.shared::cta.b64 P1, [%0], %1, 0x989680;\n\t"
        "@P1 bra.uni WD_%=;\n\t"
        "bra.uni WL_%=;\n\t"
        "WD_%=:\n\t}"
        :: "r"(a), "r"(parity) : "memory");
}
__device__ __forceinline__ void mbar_wait_cl(uint32_t a, uint32_t parity) {
    asm volatile(
        "{\n\t.reg .pred P1;\n\t"
        "WL_%=:\n\t"
        "mbarrier.try_wait.parity.acquire.cluster.shared::cta.b64 P1, [%0], %1, 0x989680;\n\t"
        "@P1 bra.uni WD_%=;\n\t"
        "bra.uni WL_%=;\n\t"
        "WD_%=:\n\t}"
        :: "r"(a), "r"(parity) : "memory");
}
// arrive on leader (rank 0) copy of an mbar at the same smem offset
__device__ __forceinline__ void arrive_leader(uint32_t local_addr) {
    asm volatile(
        "{\n\t.reg .b32 r;\n\t"
        "mapa.shared::cluster.u32 r, %0, 0;\n\t"
        "mbarrier.arrive.shared::cluster.b64 _, [r];\n\t}"
        :: "r"(local_addr) : "memory");
}
__device__ __forceinline__ void fence_proxy_all() {
    asm volatile("fence.proxy.async;" ::: "memory");
}
__device__ __forceinline__ void cluster_sync() {
    asm volatile("barrier.cluster.arrive.aligned;" ::: "memory");
    asm volatile("barrier.cluster.wait.aligned;" ::: "memory");
}
__device__ __forceinline__ void tmem_alloc_cg2(uint32_t smem_res, uint32_t ncols) {
#if TC_OK
    asm volatile("tcgen05.alloc.cta_group::2.sync.aligned.shared::cta.b32 [%0], %1;"
                 :: "r"(smem_res), "r"(ncols) : "memory");
#endif
}
__device__ __forceinline__ void tmem_relinq_cg2() {
#if TC_OK
    asm volatile("tcgen05.relinquish_alloc_permit.cta_group::2.sync.aligned;");
#endif
}
__device__ __forceinline__ void tmem_dealloc_cg2(uint32_t tmem, uint32_t ncols) {
#if TC_OK
    asm volatile("tcgen05.dealloc.cta_group::2.sync.aligned.b32 %0, %1;" :: "r"(tmem), "r"(ncols));
#endif
}
__device__ __forceinline__ void mma_commit_mc_cg2(uint32_t mbar) {
#if TC_OK
    asm volatile(
        "tcgen05.commit.cta_group::2.mbarrier::arrive::one.shared::cluster.multicast::cluster.b64 [%0], %1;"
        :: "r"(mbar), "h"((uint16_t)0x3) : "memory");
#endif
}
__device__ __forceinline__ void mma_tf32_ss_cg2(uint32_t d_tmem, uint64_t a_desc, uint64_t b_desc,
                                                uint32_t idesc, bool accum) {
#if TC_OK
    uint32_t en = accum ? 1u : 0u;
    asm volatile(
        "{\n\t.reg .pred p;\n\tsetp.ne.u32 p, %5, 0;\n\t"
        "tcgen05.mma.cta_group::2.kind::tf32 [%0], %1, %2, %3, "
        "{%4, %4, %4, %4, %4, %4, %4, %4}, p;\n\t}"
        :: "r"(d_tmem), "l"(a_desc), "l"(b_desc), "r"(idesc), "r"(0u), "r"(en)
        : "memory");
#endif
}
__device__ __forceinline__ void ldtm_x32(uint32_t* r, uint32_t tmem) {
#if TC_OK
    asm volatile(
        "tcgen05.ld.sync.aligned.32x32b.x32.b32 "
        "{%0, %1, %2, %3, %4, %5, %6, %7, %8, %9, %10, %11, %12, %13, %14, %15, "
        " %16, %17, %18, %19, %20, %21, %22, %23, %24, %25, %26, %27, %28, %29, %30, %31}, [%32];"
        : "=r"(r[0]), "=r"(r[1]), "=r"(r[2]), "=r"(r[3]), "=r"(r[4]), "=r"(r[5]), "=r"(r[6]), "=r"(r[7]),
          "=r"(r[8]), "=r"(r[9]), "=r"(r[10]), "=r"(r[11]), "=r"(r[12]), "=r"(r[13]), "=r"(r[14]), "=r"(r[15]),
          "=r"(r[16]), "=r"(r[17]), "=r"(r[18]), "=r"(r[19]), "=r"(r[20]), "=r"(r[21]), "=r"(r[22]), "=r"(r[23]),
          "=r"(r[24]), "=r"(r[25]), "=r"(r[26]), "=r"(r[27]), "=r"(r[28]), "=r"(r[29]), "=r"(r[30]), "=r"(r[31])
        : "r"(tmem));
#endif
}
__device__ __forceinline__ void tmem_wait_ld() {
#if TC_OK
    asm volatile("tcgen05.wait::ld.sync.aligned;" ::: "memory");
#endif
}
__device__ __forceinline__ void fence_after() {
#if TC_OK
    asm volatile("tcgen05.fence::after_thread_sync;" ::: "memory");
#endif
}
__device__ __forceinline__ void fence_before() {
#if TC_OK
    asm volatile("tcgen05.fence::before_thread_sync;" ::: "memory");
#endif
}

// ---------------- norms kernel ----------------
__global__ void rbf_norms_kernel(const float* __restrict__ X, const float* __restrict__ S,
                                 int N, int M) {
    int warp = (blockIdx.x * blockDim.x + threadIdx.x) >> 5;
    int lane = threadIdx.x & 31;
    if (warp >= N + M) return;
    const float* base = (warp < N) ? (X + (size_t)warp * D_DIM) : (S + (size_t)(warp - N) * D_DIM);
    float s = 0.0f;
#pragma unroll
    for (int it = 0; it < D_DIM / 128; it++) {
        float4 v = *(const float4*)(base + it * 128 + lane * 4);
        s += v.x * v.x + v.y * v.y + v.z * v.z + v.w * v.w;
    }
#pragma unroll
    for (int o = 16; o > 0; o >>= 1) s += __shfl_xor_sync(0xffffffffu, s, o);
    if (lane == 0) { if (warp < N) g_xsq[warp] = s; else g_ssq[warp - N] = s; }
}

// ---------------- per-CTA block loader (A half + B half) ----------------
__device__ __forceinline__ void load_block(uint32_t sb, const float* X, const float* S,
                                           int aRow0, int bRow0, int kb, int buf, int tid) {
    const int k0 = kb * BK;
    const uint32_t abase = sb + SM_TILE0 + buf * BUF_SZ;
    const uint32_t bbase = abase + 16384;
#pragma unroll
    for (int i = 0; i < 4; i++) {                    // A: 128 rows x 128B
        int g = tid + i * 256;
        int r = g >> 3, c = g & 7;
        uint32_t off = (uint32_t)(r * 128 + c * 16);
        uint32_t sw = off ^ ((off >> 3) & 0x70);
        cp16(abase + sw, X + (size_t)(aRow0 + r) * D_DIM + k0 + c * 4);
    }
#pragma unroll
    for (int i = 0; i < 4; i++) {                    // B half: 128 rows x 128B
        int g = tid + i * 256;
        int r = g >> 3, c = g & 7;
        uint32_t off = (uint32_t)(r * 128 + c * 16);
        uint32_t sw = off ^ ((off >> 3) & 0x70);
        cp16(bbase + sw, S + (size_t)(bRow0 + r) * D_DIM + k0 + c * 4);
    }
    cp_commit();
}

// ---------------- fused cg2 tcgen05 GEMM + RBF epilogue ----------------
__global__ void __launch_bounds__(256, 2) __cluster_dims__(2, 1, 1)
rbf_tc2_kernel(const float* __restrict__ X, const float* __restrict__ S, float* __restrict__ out) {
#if TC_OK
    extern __shared__ char smem[];
    const uint32_t sb = smem_u32(smem);
    const int tid = threadIdx.x;
    const int wid = tid >> 5, lane = tid & 31;
    const uint32_t rank = ctarank();

    const int tileM = blockIdx.x >> 1;             // 256-row tile
    const int tileN = blockIdx.y;                  // 256-col tile
    const int rowBase = tileM * 256 + (int)rank * BMH;   // this CTA's 128 rows
    const int colBase = tileN * BN;
    const int bRow0 = colBase + (int)rank * 128;   // this CTA's B (N) half

    ((float*)(smem + SM_SSQ))[tid] = g_ssq[colBase + tid];
    const int myrow = rowBase + (wid & 3) * 32 + lane;
    const float xs = g_xsq[myrow];

    if (tid == 0) {
#pragma unroll
        for (int b = 0; b < BUFS; b++) {
            mbar_init(sb + SM_FULL + b * 8, 2);
            mbar_init(sb + SM_DONE + b * 8, 1);
        }
        mbar_init(sb + SM_FIN, 1);
    }
    if (wid == 0) tmem_alloc_cg2(sb + SM_TMEMP, 256);
    __syncthreads();

    uint32_t tmem;
    asm volatile("ld.shared.b32 %0, [%1];" : "=r"(tmem) : "r"(sb + SM_TMEMP));

    // prologue: blocks 0..2 into bufs 0..2
    load_block(sb, X, S, rowBase, bRow0, 0, 0, tid);
    load_block(sb, X, S, rowBase, bRow0, 1, 1, tid);
    load_block(sb, X, S, rowBase, bRow0, 2, 2, tid);

    cluster_sync();   // mbars initialized in both CTAs before any cross arrivals

#pragma unroll
    for (int i = 0; i < NBLK; i++) {
        const int buf = i % 3;
        // local block i complete (each thread waits its own groups)
        if (i <= 5) cp_wait<2>(); else if (i == 6) cp_wait<1>(); else cp_wait<0>();
        __syncthreads();
        if (tid == 0) {
            fence_proxy_all();
            arrive_leader(sb + SM_FULL + buf * 8);
        }
        if (rank == 0 && wid == 0) {
            mbar_wait_cl(sb + SM_FULL + buf * 8, (i / 3) & 1);
            fence_proxy_all();
            if (elect_one()) {
                const uint64_t ad = MAKE_DESC(sb + SM_TILE0 + buf * BUF_SZ);
                const uint64_t bd = MAKE_DESC(sb + SM_TILE0 + buf * BUF_SZ + 16384);
#pragma unroll
                for (int s = 0; s < 4; s++)
                    mma_tf32_ss_cg2(tmem, ad + s * 2, bd + s * 2, IDESC, (i > 0) || (s > 0));
                if (i <= 4) mma_commit_mc_cg2(sb + SM_DONE + buf * 8);
                else if (i == 7) mma_commit_mc_cg2(sb + SM_FIN);
            }
        }
        if (i <= 4) {
            // reuse buf for block i+3 once MMA(i) finished reading it
            mbar_wait(sb + SM_DONE + buf * 8, (i < 3) ? 0 : 1);
            load_block(sb, X, S, rowBase, bRow0, i + 3, buf, tid);
        }
    }

    mbar_wait(sb + SM_FIN, 0);
    fence_after();

    // epilogue: 8 warps, each warp = one TMEM subpartition (wid&3) x 128-col half (wid>>2)
    const float* ssq = (const float*)(smem + SM_SSQ);
    const int half = wid >> 2;
    const float A_CONST = -0.005635527503472513f;    // -gamma * log2(e)
    const float MAGIC = 12582912.0f;                 // 1.5 * 2^23

#pragma unroll
    for (int ch = 0; ch < 4; ch++) {
        const int col0 = half * 128 + ch * 32;
        uint32_t regs[32];
        ldtm_x32(regs, tmem + col0);
        tmem_wait_ld();
        const size_t obase = (size_t)myrow * MCOLS + colBase + col0;
#pragma unroll
        for (int j4 = 0; j4 < 8; j4++) {
            float vv[4];
#pragma unroll
            for (int q = 0; q < 4; q++) {
                const int j = j4 * 4 + q;
                float cr = __uint_as_float(regs[j]);
                float d2 = fmaf(-2.0f, cr, xs + ssq[col0 + j]);
                d2 = fmaxf(d2, 0.0f);
                float t = d2 * A_CONST;
                float z = t + MAGIC;
                float r = t - (z - MAGIC);           // r in [-0.5, 0.5]
                float p = fmaf(r, 1.3333558146e-3f, 9.6181291076e-3f);
                p = fmaf(r, p, 5.5504108664e-2f);
                p = fmaf(r, p, 2.4022650696e-1f);
                p = fmaf(r, p, 6.9314718056e-1f);
                p = fmaf(r, p, 1.0f);                // 2^r
                vv[q] = __int_as_float(__float_as_int(p) + (__float_as_int(z) << 23));
            }
            *(float4*)(out + obase + j4 * 4) = make_float4(vv[0], vv[1], vv[2], vv[3]);
        }
    }

    fence_before();
    __syncthreads();
    cluster_sync();                 // both CTAs done reading TMEM before dealloc
    if (wid == 0) {
        tmem_relinq_cg2();
        tmem_dealloc_cg2(tmem, 256);
    }
    cluster_sync();
#endif  // TC_OK
}

// ---------------- SIMT fallback (proven R1 kernel) ----------------
#define FBM 128
#define FBN 128
#define FBK 32
#define FTM 8
#define FTN 8
#define FPAD 4

__global__ void __launch_bounds__(256, 2)
rbf_gemm_fallback(const float* __restrict__ X, const float* __restrict__ S,
                  float* __restrict__ out, int N, int M) {
    __shared__ float As[FBK][FBM + FPAD];
    __shared__ float Bs[FBK][FBN + FPAD];

    const int tid = threadIdx.x;
    const int tx = tid & 15;
    const int ty = tid >> 4;
    const int rowBase = blockIdx.y * FBM;
    const int colBase = blockIdx.x * FBN;

    float acc[FTM][FTN];
#pragma unroll
    for (int m = 0; m < FTM; m++)
#pragma unroll
        for (int n = 0; n < FTN; n++) acc[m][n] = 0.0f;

    for (int k0 = 0; k0 < D_DIM; k0 += FBK) {
#pragma unroll
        for (int i = 0; i < 4; i++) {
            int f = tid + i * 256;
            int r = f >> 3;
            int c = (f & 7) * 4;
            float4 a = *(const float4*)(X + (size_t)(rowBase + r) * D_DIM + k0 + c);
            As[c + 0][r] = a.x; As[c + 1][r] = a.y;
            As[c + 2][r] = a.z; As[c + 3][r] = a.w;
            float4 b = *(const float4*)(S + (size_t)(colBase + r) * D_DIM + k0 + c);
            Bs[c + 0][r] = b.x; Bs[c + 1][r] = b.y;
            Bs[c + 2][r] = b.z; Bs[c + 3][r] = b.w;
        }
        __syncthreads();

#pragma unroll 8
        for (int k = 0; k < FBK; k++) {
            float ar[FTM], br[FTN];
            float4 a0 = *(const float4*)&As[k][ty * 4];
            float4 a1 = *(const float4*)&As[k][ty * 4 + 64];
            float4 b0 = *(const float4*)&Bs[k][tx * 4];
            float4 b1 = *(const float4*)&Bs[k][tx * 4 + 64];
            ar[0] = a0.x; ar[1] = a0.y; ar[2] = a0.z; ar[3] = a0.w;
            ar[4] = a1.x; ar[5] = a1.y; ar[6] = a1.z; ar[7] = a1.w;
            br[0] = b0.x; br[1] = b0.y; br[2] = b0.z; br[3] = b0.w;
            br[4] = b1.x; br[5] = b1.y; br[6] = b1.z; br[7] = b1.w;
#pragma unroll
            for (int m = 0; m < FTM; m++)
#pragma unroll
                for (int n = 0; n < FTN; n++)
                    acc[m][n] = fmaf(ar[m], br[n], acc[m][n]);
        }
        __syncthreads();
    }

    float xsr[FTM], ssr[FTN];
#pragma unroll
    for (int m = 0; m < FTM; m++)
        xsr[m] = g_xsq[rowBase + ty * 4 + (m & 3) + (m >> 2) * 64];
#pragma unroll
    for (int n = 0; n < FTN; n++)
        ssr[n] = g_ssq[colBase + tx * 4 + (n & 3) + (n >> 2) * 64];

#pragma unroll
    for (int m = 0; m < FTM; m++) {
        int row = rowBase + ty * 4 + (m & 3) + (m >> 2) * 64;
#pragma unroll
        for (int ng = 0; ng < 2; ng++) {
            float4 v;
            float* vp = &v.x;
#pragma unroll
            for (int q = 0; q < 4; q++) {
                int n = ng * 4 + q;
                float d2 = fmaf(-2.0f, acc[m][n], xsr[m] + ssr[n]);
                d2 = fmaxf(d2, 0.0f);
                vp[q] = __expf(-GAMMA_F * d2);
            }
            int col = colBase + tx * 4 + ng * 64;
            *(float4*)(out + (size_t)row * M + col) = v;
        }
    }
}

// ---------------- launch ----------------
extern "C" void kernel_launch(void* const* d_in, const int* in_sizes, int n_in,
                              void* d_out, int out_size) {
    const float* X = (const float*)d_in[0];
    const float* S = (const float*)d_in[1];
    float* out = (float*)d_out;

    int N = in_sizes[0] / D_DIM;
    int M = in_sizes[1] / D_DIM;

    int totalWarps = N + M;
    rbf_norms_kernel<<<(totalWarps * 32 + 255) / 256, 256>>>(X, S, N, M);

    // Detect whether the loaded binary contains the tcgen05 path (guarded stub is tiny).
    cudaFuncAttributes fa;
    fa.numRegs = 0;
    cudaFuncGetAttributes(&fa, rbf_tc2_kernel);
    bool use_tc = fa.numRegs > 40;

    if (use_tc) {
        cudaFuncSetAttribute(rbf_tc2_kernel, cudaFuncAttributeMaxDynamicSharedMemorySize, SM_TOTAL);
        dim3 grid((N / 256) * 2, M / 256);   // x: 2 CTAs per 256-row tile (cluster), y: col tiles
        rbf_tc2_kernel<<<grid, 256, SM_TOTAL>>>(X, S, out);
    } else {
        dim3 grid(M / FBN, N / FBM);
        rbf_gemm_fallback<<<grid, 256>>>(X, S, out, N, M);
    }
}

// round 5
// speedup vs baseline: 1.9769x; 1.9769x over previous
#include <cuda_runtime.h>
#include <cstdint>

#define NROWS 8192
#define MCOLS 8192
#define D_DIM 256
#define GAMMA_F (1.0f/256.0f)

// ---- tensor-core path tiling ----
#define BM 128
#define BN 256
#define BK 32              // floats per k-block = 128 bytes per row
#define NBLK (D_DIM/BK)    // 8

// smem byte offsets (tc kernel, dynamic smem)
#define SM_MBAR   0        // 2 mbarriers, 8B each
#define SM_TMEMP  16
#define SM_SSQ    32       // 256 floats (premultiplied by A_CONST)
#define SM_A0     2048
#define SM_A1     (SM_A0 + BM*128)
#define SM_B0     (SM_A1 + BM*128)
#define SM_B1     (SM_B0 + BN*128)
#define SM_TOTAL  (SM_B1 + BN*128)     // 100352 B

// tf32 SS idesc: c=F32(1@[4]), a=TF32(2@[7]), b=TF32(2@[10]), N/8@[17], M/16@[24]
#define IDESC ((1u<<4) | (2u<<7) | (2u<<10) | ((BN/8u)<<17) | ((BM/16u)<<24))

// SW128 K-major smem descriptor: layout=2, version=1, SBO=64, LBO=1
#define DESC_BASE ((2ull<<61) | (1ull<<46) | (64ull<<32) | (1ull<<16))
#define MAKE_DESC(a) (DESC_BASE | ((uint64_t)((a) >> 4) & 0x3FFF))

#if defined(__CUDA_ARCH__) && (defined(__CUDA_ARCH_FEAT_SM103_ALL) || defined(__CUDA_ARCH_FEAT_SM100_ALL) || (defined(__CUDA_ARCH_SPECIFIC__) && (__CUDA_ARCH_SPECIFIC__ >= 1000)))
#define TC_OK 1
#else
#define TC_OK 0
#endif

__device__ float g_xsq[NROWS];
__device__ float g_ssq[MCOLS];

// ---------------- PTX helpers ----------------
__device__ __forceinline__ uint32_t smem_u32(const void* p) {
    uint32_t a;
    asm("{ .reg .u64 t; cvta.to.shared.u64 t, %1; cvt.u32.u64 %0, t; }" : "=r"(a) : "l"(p));
    return a;
}
__device__ __forceinline__ bool elect_one() {
    uint32_t pred;
    asm volatile("{ .reg .pred p; elect.sync _|p, 0xFFFFFFFF; selp.b32 %0, 1, 0, p; }" : "=r"(pred));
    return pred != 0;
}
__device__ __forceinline__ void cp16(uint32_t dst, const void* src) {
    asm volatile("cp.async.cg.shared.global [%0], [%1], 16;" :: "r"(dst), "l"(src));
}
__device__ __forceinline__ void cp_commit() { asm volatile("cp.async.commit_group;" ::: "memory"); }
template<int N> __device__ __forceinline__ void cp_wait() {
    asm volatile("cp.async.wait_group %0;" :: "n"(N) : "memory");
}
__device__ __forceinline__ void mbar_init(uint32_t a, uint32_t cnt) {
    asm volatile("mbarrier.init.shared.b64 [%0], %1;" :: "r"(a), "r"(cnt) : "memory");
}
__device__ __forceinline__ void mbar_wait(uint32_t a, uint32_t parity) {
    asm volatile(
        "{\n\t.reg .pred P1;\n\t"
        "WL_%=:\n\t"
        "mbarrier.try_wait.parity.acquire.cta.shared::cta.b64 P1, [%0], %1, 0x989680;\n\t"
        "@P1 bra.uni WD_%=;\n\t"
        "bra.uni WL_%=;\n\t"
        "WD_%=:\n\t}"
        :: "r"(a), "r"(parity) : "memory");
}
__device__ __forceinline__ void tmem_alloc(uint32_t smem_res, uint32_t ncols) {
#if TC_OK
    asm volatile("tcgen05.alloc.cta_group::1.sync.aligned.shared::cta.b32 [%0], %1;"
                 :: "r"(smem_res), "r"(ncols) : "memory");
#endif
}
__device__ __forceinline__ void tmem_relinq() {
#if TC_OK
    asm volatile("tcgen05.relinquish_alloc_permit.cta_group::1.sync.aligned;");
#endif
}
__device__ __forceinline__ void tmem_dealloc(uint32_t tmem, uint32_t ncols) {
#if TC_OK
    asm volatile("tcgen05.dealloc.cta_group::1.sync.aligned.b32 %0, %1;" :: "r"(tmem), "r"(ncols));
#endif
}
__device__ __forceinline__ void mma_commit(uint32_t mbar) {
#if TC_OK
    asm volatile("tcgen05.commit.cta_group::1.mbarrier::arrive::one.shared::cluster.b64 [%0];"
                 :: "r"(mbar) : "memory");
#endif
}
__device__ __forceinline__ void mma_tf32_ss(uint32_t d_tmem, uint64_t a_desc, uint64_t b_desc,
                                            uint32_t idesc, bool accum) {
#if TC_OK
    uint32_t en = accum ? 1u : 0u;
    asm volatile(
        "{\n\t.reg .pred p;\n\tsetp.ne.u32 p, %5, 0;\n\t"
        "tcgen05.mma.cta_group::1.kind::tf32 [%0], %1, %2, %3, {%4, %4, %4, %4}, p;\n\t}"
        :: "r"(d_tmem), "l"(a_desc), "l"(b_desc), "r"(idesc), "r"(0u), "r"(en)
        : "memory");
#endif
}
__device__ __forceinline__ void ldtm_x32(uint32_t* r, uint32_t tmem) {
#if TC_OK
    asm volatile(
        "tcgen05.ld.sync.aligned.32x32b.x32.b32 "
        "{%0, %1, %2, %3, %4, %5, %6, %7, %8, %9, %10, %11, %12, %13, %14, %15, "
        " %16, %17, %18, %19, %20, %21, %22, %23, %24, %25, %26, %27, %28, %29, %30, %31}, [%32];"
        : "=r"(r[0]), "=r"(r[1]), "=r"(r[2]), "=r"(r[3]), "=r"(r[4]), "=r"(r[5]), "=r"(r[6]), "=r"(r[7]),
          "=r"(r[8]), "=r"(r[9]), "=r"(r[10]), "=r"(r[11]), "=r"(r[12]), "=r"(r[13]), "=r"(r[14]), "=r"(r[15]),
          "=r"(r[16]), "=r"(r[17]), "=r"(r[18]), "=r"(r[19]), "=r"(r[20]), "=r"(r[21]), "=r"(r[22]), "=r"(r[23]),
          "=r"(r[24]), "=r"(r[25]), "=r"(r[26]), "=r"(r[27]), "=r"(r[28]), "=r"(r[29]), "=r"(r[30]), "=r"(r[31])
        : "r"(tmem));
#endif
}
__device__ __forceinline__ void tmem_wait_ld() {
#if TC_OK
    asm volatile("tcgen05.wait::ld.sync.aligned;" ::: "memory");
#endif
}
__device__ __forceinline__ void fence_after() {
#if TC_OK
    asm volatile("tcgen05.fence::after_thread_sync;" ::: "memory");
#endif
}
__device__ __forceinline__ void fence_before() {
#if TC_OK
    asm volatile("tcgen05.fence::before_thread_sync;" ::: "memory");
#endif
}
__device__ __forceinline__ void fence_proxy() {
    asm volatile("fence.proxy.async.shared::cta;" ::: "memory");
}

// ---- packed f32x2 helpers (sm_103a) ----
__device__ __forceinline__ uint64_t pack2(uint32_t lo, uint32_t hi) {
    uint64_t r;
    asm("mov.b64 %0, {%1, %2};" : "=l"(r) : "r"(lo), "r"(hi));
    return r;
}
__device__ __forceinline__ void unpack2(uint32_t& lo, uint32_t& hi, uint64_t v) {
    asm("mov.b64 {%0, %1}, %2;" : "=r"(lo), "=r"(hi) : "l"(v));
}
#if TC_OK
#define FMA2(d, a, b, c) asm("fma.rn.f32x2 %0, %1, %2, %3;" : "=l"(d) : "l"(a), "l"(b), "l"(c))
#define ADD2(d, a, b)    asm("add.rn.f32x2 %0, %1, %2;" : "=l"(d) : "l"(a), "l"(b))
#endif

// ---------------- norms kernel ----------------
__global__ void rbf_norms_kernel(const float* __restrict__ X, const float* __restrict__ S,
                                 int N, int M) {
    int warp = (blockIdx.x * blockDim.x + threadIdx.x) >> 5;
    int lane = threadIdx.x & 31;
    if (warp >= N + M) return;
    const float* base = (warp < N) ? (X + (size_t)warp * D_DIM) : (S + (size_t)(warp - N) * D_DIM);
    float s = 0.0f;
#pragma unroll
    for (int it = 0; it < D_DIM / 128; it++) {
        float4 v = *(const float4*)(base + it * 128 + lane * 4);
        s += v.x * v.x + v.y * v.y + v.z * v.z + v.w * v.w;
    }
#pragma unroll
    for (int o = 16; o > 0; o >>= 1) s += __shfl_xor_sync(0xffffffffu, s, o);
    if (lane == 0) { if (warp < N) g_xsq[warp] = s; else g_ssq[warp - N] = s; }
}

// ---------------- tc-path block loader ----------------
__device__ __forceinline__ void load_block(uint32_t sb, const float* X, const float* S,
                                           int rowBase, int colBase, int kb, int buf, int tid) {
    const int k0 = kb * BK;
    const uint32_t abase = sb + (buf ? SM_A1 : SM_A0);
    const uint32_t bbase = sb + (buf ? SM_B1 : SM_B0);
#pragma unroll
    for (int i = 0; i < 4; i++) {                    // A: 128 rows x 128B
        int g = tid + i * 256;
        int r = g >> 3, c = g & 7;
        uint32_t off = (uint32_t)(r * 128 + c * 16);
        uint32_t sw = off ^ ((off >> 3) & 0x70);
        cp16(abase + sw, X + (size_t)(rowBase + r) * D_DIM + k0 + c * 4);
    }
#pragma unroll
    for (int i = 0; i < 8; i++) {                    // B: 256 rows x 128B
        int g = tid + i * 256;
        int r = g >> 3, c = g & 7;
        uint32_t off = (uint32_t)(r * 128 + c * 16);
        uint32_t sw = off ^ ((off >> 3) & 0x70);
        cp16(bbase + sw, S + (size_t)(colBase + r) * D_DIM + k0 + c * 4);
    }
    cp_commit();
}

// ---------------- fused tcgen05 GEMM + RBF epilogue ----------------
__global__ void __launch_bounds__(256, 2)
rbf_tc_kernel(const float* __restrict__ X, const float* __restrict__ S, float* __restrict__ out) {
#if TC_OK
    extern __shared__ char smem[];
    const uint32_t sb = smem_u32(smem);
    const int tid = threadIdx.x;
    const int wid = tid >> 5, lane = tid & 31;
    const int rowBase = blockIdx.y * BM;
    const int colBase = blockIdx.x * BN;

    const float A_CONST = -0.005635527503472513f;    // -gamma * log2(e)

    // premultiplied ssq tile -> smem; premultiplied xsq -> reg
    ((float*)(smem + SM_SSQ))[tid] = A_CONST * g_ssq[colBase + tid];
    const int sub = wid & 3;
    const int myrow = rowBase + sub * 32 + lane;
    const float xsA = A_CONST * g_xsq[myrow];

    if (tid == 0) { mbar_init(sb + SM_MBAR, 1); mbar_init(sb + SM_MBAR + 8, 1); }
    if (wid == 0) { tmem_alloc(sb + SM_TMEMP, 256); tmem_relinq(); }

    load_block(sb, X, S, rowBase, colBase, 0, 0, tid);
    load_block(sb, X, S, rowBase, colBase, 1, 1, tid);
    __syncthreads();

    uint32_t tmem;
    asm volatile("ld.shared.b32 %0, [%1];" : "=r"(tmem) : "r"(sb + SM_TMEMP));

    const uint64_t ad0 = MAKE_DESC(sb + SM_A0), ad1 = MAKE_DESC(sb + SM_A1);
    const uint64_t bd0 = MAKE_DESC(sb + SM_B0), bd1 = MAKE_DESC(sb + SM_B1);

#pragma unroll
    for (int i = 0; i < NBLK; i++) {
        if (i < NBLK - 1) cp_wait<1>(); else cp_wait<0>();
        __syncthreads();
        if (wid == 0) {
            fence_proxy();
            if (elect_one()) {
                const uint64_t ad = (i & 1) ? ad1 : ad0;
                const uint64_t bd = (i & 1) ? bd1 : bd0;
#pragma unroll
                for (int s = 0; s < 4; s++)   // 4 x K=8 tf32 steps
                    mma_tf32_ss(tmem, ad + s * 2, bd + s * 2, IDESC, (i > 0) || (s > 0));
                mma_commit(sb + SM_MBAR + (i & 1) * 8);
            }
        }
        if (i + 2 < NBLK) {
            mbar_wait(sb + SM_MBAR + (i & 1) * 8, (i >> 1) & 1);
            load_block(sb, X, S, rowBase, colBase, i + 2, i & 1, tid);
        }
    }
    mbar_wait(sb + SM_MBAR + 8, 1);
    fence_after();

    // ---- packed f32x2 epilogue ----
    // t = A*d2 = xsA + ssqA[j] + (-2A)*cross ; out = 2^t via magic-add range reduction
    const float C2 = -2.0f * A_CONST;                // positive
    const float MAGIC = 12582912.0f;                 // 1.5 * 2^23
    const uint64_t xsAp   = pack2(__float_as_uint(xsA), __float_as_uint(xsA));
    const uint64_t C2p    = pack2(__float_as_uint(C2), __float_as_uint(C2));
    const uint64_t MAGICp = pack2(__float_as_uint(MAGIC), __float_as_uint(MAGIC));
    const uint64_t NMAGp  = pack2(__float_as_uint(-MAGIC), __float_as_uint(-MAGIC));
    const uint64_t NEG1p  = pack2(__float_as_uint(-1.0f), __float_as_uint(-1.0f));
    const uint64_t C4p = pack2(__float_as_uint(9.6181291e-3f), __float_as_uint(9.6181291e-3f));
    const uint64_t C3p = pack2(__float_as_uint(5.5504115e-2f), __float_as_uint(5.5504115e-2f));
    const uint64_t C2pp = pack2(__float_as_uint(2.4022649e-1f), __float_as_uint(2.4022649e-1f));
    const uint64_t C1p = pack2(__float_as_uint(6.9314718e-1f), __float_as_uint(6.9314718e-1f));
    const uint64_t C0p = pack2(__float_as_uint(1.0f), __float_as_uint(1.0f));

    const char* ssqA = (const char*)(smem + SM_SSQ);
    const int half = wid >> 2;

#pragma unroll
    for (int ch = 0; ch < 4; ch++) {
        const int col0 = half * 128 + ch * 32;
        uint32_t regs[32];
        ldtm_x32(regs, tmem + col0);
        tmem_wait_ld();
        const size_t obase = (size_t)myrow * MCOLS + colBase + col0;
#pragma unroll
        for (int j4 = 0; j4 < 8; j4++) {
            float vv[4];
#pragma unroll
            for (int jp = 0; jp < 2; jp++) {
                const int j = j4 * 4 + jp * 2;
                uint64_t sAp = *(const uint64_t*)(ssqA + (col0 + j) * 4);
                uint64_t crp = pack2(regs[j], regs[j + 1]);
                uint64_t up, tp, zp, yp, rp, pp;
                ADD2(up, sAp, xsAp);
                FMA2(tp, crp, C2p, up);
                ADD2(zp, tp, MAGICp);
                ADD2(yp, zp, NMAGp);                 // y = z - MAGIC
                FMA2(rp, yp, NEG1p, tp);             // r = t - y
                FMA2(pp, rp, C4p, C3p);
                FMA2(pp, rp, pp, C2pp);
                FMA2(pp, rp, pp, C1p);
                FMA2(pp, rp, pp, C0p);               // 2^r
                uint32_t z0, z1, p0, p1;
                unpack2(z0, z1, zp);
                unpack2(p0, p1, pp);
                vv[jp * 2 + 0] = __int_as_float((int)p0 + ((int)z0 << 23));
                vv[jp * 2 + 1] = __int_as_float((int)p1 + ((int)z1 << 23));
            }
            *(float4*)(out + obase + j4 * 4) = make_float4(vv[0], vv[1], vv[2], vv[3]);
        }
    }

    fence_before();
    __syncthreads();
    if (wid == 0) tmem_dealloc(tmem, 256);
#endif  // TC_OK
}

// ---------------- SIMT fallback (proven R1 kernel) ----------------
#define FBM 128
#define FBN 128
#define FBK 32
#define FTM 8
#define FTN 8
#define FPAD 4

__global__ void __launch_bounds__(256, 2)
rbf_gemm_fallback(const float* __restrict__ X, const float* __restrict__ S,
                  float* __restrict__ out, int N, int M) {
    __shared__ float As[FBK][FBM + FPAD];
    __shared__ float Bs[FBK][FBN + FPAD];

    const int tid = threadIdx.x;
    const int tx = tid & 15;
    const int ty = tid >> 4;
    const int rowBase = blockIdx.y * FBM;
    const int colBase = blockIdx.x * FBN;

    float acc[FTM][FTN];
#pragma unroll
    for (int m = 0; m < FTM; m++)
#pragma unroll
        for (int n = 0; n < FTN; n++) acc[m][n] = 0.0f;

    for (int k0 = 0; k0 < D_DIM; k0 += FBK) {
#pragma unroll
        for (int i = 0; i < 4; i++) {
            int f = tid + i * 256;
            int r = f >> 3;
            int c = (f & 7) * 4;
            float4 a = *(const float4*)(X + (size_t)(rowBase + r) * D_DIM + k0 + c);
            As[c + 0][r] = a.x; As[c + 1][r] = a.y;
            As[c + 2][r] = a.z; As[c + 3][r] = a.w;
            float4 b = *(const float4*)(S + (size_t)(colBase + r) * D_DIM + k0 + c);
            Bs[c + 0][r] = b.x; Bs[c + 1][r] = b.y;
            Bs[c + 2][r] = b.z; Bs[c + 3][r] = b.w;
        }
        __syncthreads();

#pragma unroll 8
        for (int k = 0; k < FBK; k++) {
            float ar[FTM], br[FTN];
            float4 a0 = *(const float4*)&As[k][ty * 4];
            float4 a1 = *(const float4*)&As[k][ty * 4 + 64];
            float4 b0 = *(const float4*)&Bs[k][tx * 4];
            float4 b1 = *(const float4*)&Bs[k][tx * 4 + 64];
            ar[0] = a0.x; ar[1] = a0.y; ar[2] = a0.z; ar[3] = a0.w;
            ar[4] = a1.x; ar[5] = a1.y; ar[6] = a1.z; ar[7] = a1.w;
            br[0] = b0.x; br[1] = b0.y; br[2] = b0.z; br[3] = b0.w;
            br[4] = b1.x; br[5] = b1.y; br[6] = b1.z; br[7] = b1.w;
#pragma unroll
            for (int m = 0; m < FTM; m++)
#pragma unroll
                for (int n = 0; n < FTN; n++)
                    acc[m][n] = fmaf(ar[m], br[n], acc[m][n]);
        }
        __syncthreads();
    }

    float xsr[FTM], ssr[FTN];
#pragma unroll
    for (int m = 0; m < FTM; m++)
        xsr[m] = g_xsq[rowBase + ty * 4 + (m & 3) + (m >> 2) * 64];
#pragma unroll
    for (int n = 0; n < FTN; n++)
        ssr[n] = g_ssq[colBase + tx * 4 + (n & 3) + (n >> 2) * 64];

#pragma unroll
    for (int m = 0; m < FTM; m++) {
        int row = rowBase + ty * 4 + (m & 3) + (m >> 2) * 64;
#pragma unroll
        for (int ng = 0; ng < 2; ng++) {
            float4 v;
            float* vp = &v.x;
#pragma unroll
            for (int q = 0; q < 4; q++) {
                int n = ng * 4 + q;
                float d2 = fmaf(-2.0f, acc[m][n], xsr[m] + ssr[n]);
                d2 = fmaxf(d2, 0.0f);
                vp[q] = __expf(-GAMMA_F * d2);
            }
            int col = colBase + tx * 4 + ng * 64;
            *(float4*)(out + (size_t)row * M + col) = v;
        }
    }
}

// ---------------- launch ----------------
extern "C" void kernel_launch(void* const* d_in, const int* in_sizes, int n_in,
                              void* d_out, int out_size) {
    const float* X = (const float*)d_in[0];
    const float* S = (const float*)d_in[1];
    float* out = (float*)d_out;

    int N = in_sizes[0] / D_DIM;
    int M = in_sizes[1] / D_DIM;

    int totalWarps = N + M;
    rbf_norms_kernel<<<(totalWarps * 32 + 255) / 256, 256>>>(X, S, N, M);

    cudaFuncAttributes fa;
    fa.numRegs = 0;
    cudaFuncGetAttributes(&fa, rbf_tc_kernel);
    bool use_tc = fa.numRegs > 40;

    if (use_tc) {
        cudaFuncSetAttribute(rbf_tc_kernel, cudaFuncAttributeMaxDynamicSharedMemorySize, SM_TOTAL);
        dim3 grid(M / BN, N / BM);
        rbf_tc_kernel<<<grid, 256, SM_TOTAL>>>(X, S, out);
    } else {
        dim3 grid(M / FBN, N / FBM);
        rbf_gemm_fallback<<<grid, 256>>>(X, S, out, N, M);
    }
}